// round 9
// baseline (speedup 1.0000x reference)
#include <cuda_runtime.h>
#include <math.h>

// ---------------------------------------------------------------------------
// Gate templates (compile-time masks). Wire w <-> bit (3-w) of amp index.
// ---------------------------------------------------------------------------
template<int M>
__device__ __forceinline__ void ry_gate(float sr[16], float si[16], float c, float s) {
#pragma unroll
    for (int i = 0; i < 16; i++) {
        if (!(i & M)) {
            const int j = i | M;
            float a0r = sr[i], a0i = si[i], a1r = sr[j], a1i = si[j];
            sr[i] = c * a0r - s * a1r;
            si[i] = c * a0i - s * a1i;
            sr[j] = s * a0r + c * a1r;
            si[j] = s * a0i + c * a1i;
        }
    }
}

template<int M>
__device__ __forceinline__ void rz_gate(float sr[16], float si[16], float c, float s) {
#pragma unroll
    for (int i = 0; i < 16; i++) {
        float sg = (i & M) ? s : -s;
        float rr = sr[i], ii = si[i];
        sr[i] = c * rr - sg * ii;
        si[i] = c * ii + sg * rr;
    }
}

template<int CM, int TM>
__device__ __forceinline__ void cx_gate(float sr[16], float si[16]) {
#pragma unroll
    for (int i = 0; i < 16; i++) {
        if ((i & CM) && !(i & TM)) {
            const int j = i | TM;
            float t;
            t = sr[i]; sr[i] = sr[j]; sr[j] = t;
            t = si[i]; si[i] = si[j]; si[j] = t;
        }
    }
}

// Factored inner product over 12-padded row: t = aw . (u2 (x) v3), 8 FMA.
__device__ __forceinline__ float dot9p(const float aw[12], float c2, float s2, float c3, float s3) {
    float m0 = fmaf(c3, aw[1], aw[0]); m0 = fmaf(s3, aw[2], m0);
    float m1 = fmaf(c3, aw[4], aw[3]); m1 = fmaf(s3, aw[5], m1);
    float m2 = fmaf(c3, aw[7], aw[6]); m2 = fmaf(s3, aw[8], m2);
    float t  = fmaf(c2, m1, m0);
    return fmaf(s2, m2, t);
}

// ---------------------------------------------------------------------------
// Single persistent kernel. Each block:
//   1) builds the 4x81 multilinear coefficient tensor A in its own smem
//      (scratch overlaid on the feats buffer),
//   2) grid-strides over image-quads: contraction -> warp-GEMM -> log_softmax.
// ---------------------------------------------------------------------------
__global__ __launch_bounds__(224, 4) void quanv_persist_kernel(
    const float* __restrict__ x,     // (B,1,28,28)
    const float* __restrict__ vp,    // (3,8)
    const float* __restrict__ W,     // (10,784)
    const float* __restrict__ bias,  // (10,)
    float* __restrict__ out,         // (B,10)
    int B, int nQuads)
{
    const int tid  = threadIdx.x;
    const int warp = tid >> 5;
    const int lane = tid & 31;

    __shared__ float vc[24], vs[24];
    __shared__ __align__(16) float sA[9 * 4 * 12];
    __shared__ float slog[40];
    __shared__ float slse[4];
    // Overlay: precompute scratch (Ur 256 + Ui 256 + ReO 1024 floats = 6KB)
    // reuses the feats buffer (4*196 float4 = 12544 bytes).
    __shared__ __align__(16) float ovl[3136];

    float (*Ur)[16]      = reinterpret_cast<float(*)[16]>(ovl);
    float (*Ui)[16]      = reinterpret_cast<float(*)[16]>(ovl + 256);
    float (*ReO)[16][16] = reinterpret_cast<float(*)[16][16]>(ovl + 512);
    float4 (*feats)[196] = reinterpret_cast<float4(*)[196]>(ovl);

    // ================= inline precompute of A (per block) =================
    if (tid < 24) {
        float ss, cc;
        __sincosf(vp[tid] * 0.5f, &ss, &cc);
        vc[tid] = cc;
        vs[tid] = ss;
    }
    __syncthreads();

    if (tid < 16) {
        float sr[16], si[16];
#pragma unroll
        for (int i = 0; i < 16; i++) { sr[i] = 0.0f; si[i] = 0.0f; }
        sr[tid] = 1.0f;

#pragma unroll
        for (int l = 0; l < 3; l++) {
            const float* lc = vc + l * 8;
            const float* ls = vs + l * 8;
            ry_gate<8>(sr, si, lc[0], ls[0]); rz_gate<8>(sr, si, lc[1], ls[1]);
            ry_gate<4>(sr, si, lc[1], ls[1]); rz_gate<4>(sr, si, lc[2], ls[2]);
            ry_gate<2>(sr, si, lc[2], ls[2]); rz_gate<2>(sr, si, lc[3], ls[3]);
            ry_gate<1>(sr, si, lc[3], ls[3]); rz_gate<1>(sr, si, lc[4], ls[4]);
            cx_gate<8, 4>(sr, si);
            cx_gate<4, 2>(sr, si);
            cx_gate<2, 1>(sr, si);
            cx_gate<1, 8>(sr, si);
        }
#pragma unroll
        for (int k = 0; k < 16; k++) { Ur[k][tid] = sr[k]; Ui[k][tid] = si[k]; }
    }
    __syncthreads();

    for (int t = tid; t < 256; t += 224) {
        const int i = t >> 4;
        const int j = t & 15;
        float acc[4] = {0.0f, 0.0f, 0.0f, 0.0f};
#pragma unroll
        for (int k = 0; k < 16; k++) {
            float v = Ur[k][i] * Ur[k][j] + Ui[k][i] * Ui[k][j];
#pragma unroll
            for (int w = 0; w < 4; w++)
                acc[w] += (k & (8 >> w)) ? -v : v;
        }
#pragma unroll
        for (int w = 0; w < 4; w++) ReO[w][i][j] = acc[w];
    }
    __syncthreads();

    for (int t = tid; t < 432; t += 224) {
        const int a12 = t / 48;          // 0..8
        const int w   = (t / 12) & 3;    // 0..3
        const int a34 = t % 12;          // 0..11 (9..11 = pad)
        float val = 0.0f;
        if (a34 < 9) {
            const int a0 = a12 / 3, a1 = a12 % 3;
            const int a2 = a34 / 3, a3 = a34 % 3;
            const int zm = (a0 == 1 ? 8 : 0) | (a1 == 1 ? 4 : 0) | (a2 == 1 ? 2 : 0) | (a3 == 1 ? 1 : 0);
            const int xm = (a0 == 2 ? 8 : 0) | (a1 == 2 ? 4 : 0) | (a2 == 2 ? 2 : 0) | (a3 == 2 ? 1 : 0);
            float acc = 0.0f;
#pragma unroll
            for (int i = 0; i < 16; i++) {
                float v = ReO[w][i][i ^ xm];
                acc += (__popc(i & zm) & 1) ? -v : v;
            }
            val = acc * 0.0625f;
        }
        sA[t] = val;   // (a12*4 + w)*12 + a34 == t
    }
    __syncthreads();   // sA ready; ovl free for feats

    // ===================== persistent loop over image-quads =====================
    for (int q = blockIdx.x; q < nQuads; q += gridDim.x) {
        const int b0 = 4 * q;

        if (tid < 196) {
            const int r14 = tid / 14;
            const int c14 = tid % 14;
            const int off = (2 * r14) * 28 + 2 * c14;

            float cs[4][8];
#pragma unroll
            for (int m = 0; m < 4; m++) {
                int b = b0 + m;
                if (b >= B) b = B - 1;               // duplicate work, writes masked
                const float* xb = x + (size_t)b * 784;
                const float2 t2 = *reinterpret_cast<const float2*>(xb + off);
                const float2 d2 = *reinterpret_cast<const float2*>(xb + off + 28);
                __sincosf(t2.x, &cs[m][1], &cs[m][0]);
                __sincosf(t2.y, &cs[m][3], &cs[m][2]);
                __sincosf(d2.x, &cs[m][5], &cs[m][4]);
                __sincosf(d2.y, &cs[m][7], &cs[m][6]);
            }

            float e[4][4];
#pragma unroll
            for (int m = 0; m < 4; m++)
#pragma unroll
                for (int w = 0; w < 4; w++) e[m][w] = 0.0f;

#pragma unroll
            for (int i = 0; i < 9; i++) {
                float ga[4];
#pragma unroll
                for (int m = 0; m < 4; m++) {
                    const int iu = i / 3, iv = i % 3;
                    const float u = (iu == 0) ? 1.0f : (iu == 1 ? cs[m][0] : cs[m][1]);
                    const float v = (iv == 0) ? 1.0f : (iv == 1 ? cs[m][2] : cs[m][3]);
                    ga[m] = u * v;
                }
#pragma unroll
                for (int w = 0; w < 4; w++) {
                    float aw[12];
#pragma unroll
                    for (int p = 0; p < 3; p++)
                        *reinterpret_cast<float4*>(aw + 4 * p) =
                            *reinterpret_cast<const float4*>(&sA[(i * 4 + w) * 12 + 4 * p]);
#pragma unroll
                    for (int m = 0; m < 4; m++) {
                        const float t = dot9p(aw, cs[m][4], cs[m][5], cs[m][6], cs[m][7]);
                        e[m][w] = fmaf(ga[m], t, e[m][w]);
                    }
                }
            }

#pragma unroll
            for (int m = 0; m < 4; m++)
                feats[m][tid] = make_float4(e[m][0], e[m][1], e[m][2], e[m][3]);
        }
        __syncthreads();

        // ---- warp-GEMM logits: 40 tasks (img,class) over 7 warps ----
#pragma unroll
        for (int r = 0; r < 6; r++) {
            const int task = warp + 7 * r;
            if (task < 40) {
                const int img = task / 10;
                const int c   = task % 10;
                const float* wrow = W + c * 784;
                float acc = 0.0f;
#pragma unroll
                for (int k = 0; k < 6; k++) {
                    const int p = 32 * k + lane;
                    const float4 fv = feats[img][p];
                    const float4 wv = *reinterpret_cast<const float4*>(wrow + 4 * p);
                    acc = fmaf(fv.x, wv.x, acc);
                    acc = fmaf(fv.y, wv.y, acc);
                    acc = fmaf(fv.z, wv.z, acc);
                    acc = fmaf(fv.w, wv.w, acc);
                }
                if (lane < 4) {
                    const int p = 192 + lane;
                    const float4 fv = feats[img][p];
                    const float4 wv = *reinterpret_cast<const float4*>(wrow + 4 * p);
                    acc = fmaf(fv.x, wv.x, acc);
                    acc = fmaf(fv.y, wv.y, acc);
                    acc = fmaf(fv.z, wv.z, acc);
                    acc = fmaf(fv.w, wv.w, acc);
                }
#pragma unroll
                for (int off = 16; off > 0; off >>= 1)
                    acc += __shfl_xor_sync(0xffffffffu, acc, off);
                if (lane == 0) slog[task] = acc + bias[c];
            }
        }
        __syncthreads();

        if (tid < 4) {
            const float* l = slog + 10 * tid;
            float mx = l[0];
#pragma unroll
            for (int c = 1; c < 10; c++) mx = fmaxf(mx, l[c]);
            float se = 0.0f;
#pragma unroll
            for (int c = 0; c < 10; c++) se += expf(l[c] - mx);
            slse[tid] = mx + logf(se);
        }
        __syncthreads();

        if (tid < 40) {
            const int img = tid / 10;
            const int b = b0 + img;
            if (b < B)
                out[(size_t)b * 10 + (tid % 10)] = slog[tid] - slse[img];
        }
        __syncthreads();   // protect feats/slog before next quad
    }
}

extern "C" void kernel_launch(void* const* d_in, const int* in_sizes, int n_in,
                              void* d_out, int out_size) {
    const float* x    = (const float*)d_in[0];   // (B,1,28,28)
    const float* vp   = (const float*)d_in[1];   // (3,8)
    const float* W    = (const float*)d_in[2];   // (10,784)
    const float* bias = (const float*)d_in[3];   // (10,)
    float* out = (float*)d_out;

    const int B = in_sizes[0] / 784;
    const int nQuads = (B + 3) / 4;
    int grid = 4 * 148;                 // 4 blocks/SM x 148 SMs
    if (grid > nQuads) grid = nQuads;
    quanv_persist_kernel<<<grid, 224>>>(x, vp, W, bias, out, B, nQuads);
}

// round 10
// speedup vs baseline: 1.2713x; 1.2713x over previous
#include <cuda_runtime.h>
#include <math.h>

// Coefficient tensor, layout [i(a12)][w][12]: j at 0..8, pad 9..11.
__device__ float g_A[9 * 4 * 12];

// ---------------------------------------------------------------------------
// Fast precompute kernel: 256 threads = (amp i = tid%16, column j = tid/16).
// Gates via __shfl_xor_sync within 16-lane groups (masks 1,2,4,8 < 16).
// Then ReO and the multilinear coefficient tensor A.
// ---------------------------------------------------------------------------
__global__ void precompute_A_fast_kernel(const float* __restrict__ vp) {
    __shared__ float vc[24], vs[24];
    __shared__ float Ur[16][16], Ui[16][16];   // [amp i][column j]
    __shared__ float ReO[4][16][16];

    const int tid = threadIdx.x;
    const int i   = tid & 15;    // amplitude index
    const int j   = tid >> 4;    // basis column

    if (tid < 24) {
        float ss, cc;
        __sincosf(vp[tid] * 0.5f, &ss, &cc);
        vc[tid] = cc;
        vs[tid] = ss;
    }
    __syncthreads();

    // amp[i][j] of U, evolved from identity
    float ar = (i == j) ? 1.0f : 0.0f;
    float ai = 0.0f;

#pragma unroll
    for (int l = 0; l < 3; l++) {
        const float* lc = vc + l * 8;
        const float* ls = vs + l * 8;
        // wires 0..3: RY(p[k]) then RZ(p[k+1]); wire w <-> mask 8>>w
#pragma unroll
        for (int k = 0; k < 4; k++) {
            const int M = 8 >> k;
            const float cy = lc[k],     sy = ls[k];
            const float cz = lc[k + 1], sz = ls[k + 1];
            // RY
            const float orr = __shfl_xor_sync(0xffffffffu, ar, M);
            const float oii = __shfl_xor_sync(0xffffffffu, ai, M);
            const float sgn = (i & M) ? sy : -sy;
            ar = fmaf(sgn, orr, cy * ar);
            ai = fmaf(sgn, oii, cy * ai);
            // RZ: bit clear -> phase (cz, -sz) i.e. r' = cz*r + sz*im? careful:
            // bit0: multiply by exp(-i th/2) = (cz - i sz): r' = cz*r + sz*im, im' = cz*im - sz*r
            // bit1: conj phase
            const float sg = (i & M) ? -sz : sz;
            const float rr = ar, im = ai;
            ar = fmaf(sg, im, cz * rr);
            ai = fmaf(-sg, rr, cz * im);
        }
        // CX ring: (c,t) = (0,1),(1,2),(2,3),(3,0) -> masks (8,4),(4,2),(2,1),(1,8)
#pragma unroll
        for (int k = 0; k < 4; k++) {
            const int CM = 8 >> k;
            const int TM = (k == 3) ? 8 : (4 >> k);
            const float orr = __shfl_xor_sync(0xffffffffu, ar, TM);
            const float oii = __shfl_xor_sync(0xffffffffu, ai, TM);
            if (i & CM) { ar = orr; ai = oii; }
        }
    }

    Ur[i][j] = ar;
    Ui[i][j] = ai;
    __syncthreads();

    // ReO_w[p][q] = sum_k z_w(k) (Ur[k][p]Ur[k][q] + Ui[k][p]Ui[k][q])
    {
        const int p = tid >> 4;
        const int q = tid & 15;
        float acc[4] = {0.0f, 0.0f, 0.0f, 0.0f};
#pragma unroll
        for (int k = 0; k < 16; k++) {
            const float t = Ur[k][p] * Ur[k][q] + Ui[k][p] * Ui[k][q];
#pragma unroll
            for (int w = 0; w < 4; w++)
                acc[w] += (k & (8 >> w)) ? -t : t;
        }
#pragma unroll
        for (int w = 0; w < 4; w++) ReO[w][p][q] = acc[w];
    }
    __syncthreads();

    // A[(a12*4+w)*12 + a34] (pad a34 = 9..11 with 0)
    for (int t = tid; t < 432; t += 256) {
        const int a12 = t / 48;
        const int w   = (t / 12) & 3;
        const int a34 = t % 12;
        float val = 0.0f;
        if (a34 < 9) {
            const int a0 = a12 / 3, a1 = a12 % 3;
            const int a2 = a34 / 3, a3 = a34 % 3;
            const int zm = (a0 == 1 ? 8 : 0) | (a1 == 1 ? 4 : 0) | (a2 == 1 ? 2 : 0) | (a3 == 1 ? 1 : 0);
            const int xm = (a0 == 2 ? 8 : 0) | (a1 == 2 ? 4 : 0) | (a2 == 2 ? 2 : 0) | (a3 == 2 ? 1 : 0);
            float acc = 0.0f;
#pragma unroll
            for (int p = 0; p < 16; p++) {
                const float v = ReO[w][p][p ^ xm];
                acc += (__popc(p & zm) & 1) ? -v : v;
            }
            val = acc * 0.0625f;
        }
        g_A[t] = val;
    }
}

// Factored inner product over 12-padded row: t = aw . (u2 (x) v3), 8 FMA.
__device__ __forceinline__ float dot9p(const float aw[12], float c2, float s2, float c3, float s3) {
    float m0 = fmaf(c3, aw[1], aw[0]); m0 = fmaf(s3, aw[2], m0);
    float m1 = fmaf(c3, aw[4], aw[3]); m1 = fmaf(s3, aw[5], m1);
    float m2 = fmaf(c3, aw[7], aw[6]); m2 = fmaf(s3, aw[8], m2);
    float t  = fmaf(c2, m1, m0);
    return fmaf(s2, m2, t);
}

// ---------------------------------------------------------------------------
// Main fused kernel (identical to R8): one block per 4 IMAGES.
// ---------------------------------------------------------------------------
__global__ __launch_bounds__(224, 4) void quanv_fused8_kernel(
    const float* __restrict__ x,     // (B,1,28,28)
    const float* __restrict__ W,     // (10,784)
    const float* __restrict__ bias,  // (10,)
    float* __restrict__ out,         // (B,10)
    int B)
{
    const int b0   = 4 * blockIdx.x;
    const int tid  = threadIdx.x;
    const int warp = tid >> 5;
    const int lane = tid & 31;

    __shared__ __align__(16) float sA[9 * 4 * 12];
    __shared__ __align__(16) float4 feats[4][196];
    __shared__ float slog[40];
    __shared__ float slse[4];

    for (int i = tid; i < 9 * 4 * 12; i += 224)
        sA[i] = g_A[i];
    __syncthreads();

    if (tid < 196) {
        const int r14 = tid / 14;
        const int c14 = tid % 14;
        const int off = (2 * r14) * 28 + 2 * c14;

        float cs[4][8];
#pragma unroll
        for (int m = 0; m < 4; m++) {
            int b = b0 + m;
            if (b >= B) b = B - 1;               // duplicate work, writes masked later
            const float* xb = x + (size_t)b * 784;
            const float2 t2 = *reinterpret_cast<const float2*>(xb + off);
            const float2 d2 = *reinterpret_cast<const float2*>(xb + off + 28);
            __sincosf(t2.x, &cs[m][1], &cs[m][0]);
            __sincosf(t2.y, &cs[m][3], &cs[m][2]);
            __sincosf(d2.x, &cs[m][5], &cs[m][4]);
            __sincosf(d2.y, &cs[m][7], &cs[m][6]);
        }

        float e[4][4];
#pragma unroll
        for (int m = 0; m < 4; m++)
#pragma unroll
            for (int w = 0; w < 4; w++) e[m][w] = 0.0f;

#pragma unroll
        for (int i = 0; i < 9; i++) {
            float ga[4];
#pragma unroll
            for (int m = 0; m < 4; m++) {
                const int iu = i / 3, iv = i % 3;
                const float u = (iu == 0) ? 1.0f : (iu == 1 ? cs[m][0] : cs[m][1]);
                const float v = (iv == 0) ? 1.0f : (iv == 1 ? cs[m][2] : cs[m][3]);
                ga[m] = u * v;
            }
#pragma unroll
            for (int w = 0; w < 4; w++) {
                float aw[12];
#pragma unroll
                for (int q = 0; q < 3; q++)
                    *reinterpret_cast<float4*>(aw + 4 * q) =
                        *reinterpret_cast<const float4*>(&sA[(i * 4 + w) * 12 + 4 * q]);
#pragma unroll
                for (int m = 0; m < 4; m++) {
                    const float t = dot9p(aw, cs[m][4], cs[m][5], cs[m][6], cs[m][7]);
                    e[m][w] = fmaf(ga[m], t, e[m][w]);
                }
            }
        }

#pragma unroll
        for (int m = 0; m < 4; m++)
            feats[m][tid] = make_float4(e[m][0], e[m][1], e[m][2], e[m][3]);
    }
    __syncthreads();

    // ---- warp-GEMM logits: 40 tasks (img,class) over 7 warps ----
#pragma unroll
    for (int r = 0; r < 6; r++) {
        const int task = warp + 7 * r;
        if (task < 40) {
            const int img = task / 10;
            const int c   = task % 10;
            const float* wrow = W + c * 784;
            float acc = 0.0f;
#pragma unroll
            for (int k = 0; k < 6; k++) {
                const int p = 32 * k + lane;
                const float4 fv = feats[img][p];
                const float4 wv = *reinterpret_cast<const float4*>(wrow + 4 * p);
                acc = fmaf(fv.x, wv.x, acc);
                acc = fmaf(fv.y, wv.y, acc);
                acc = fmaf(fv.z, wv.z, acc);
                acc = fmaf(fv.w, wv.w, acc);
            }
            if (lane < 4) {
                const int p = 192 + lane;
                const float4 fv = feats[img][p];
                const float4 wv = *reinterpret_cast<const float4*>(wrow + 4 * p);
                acc = fmaf(fv.x, wv.x, acc);
                acc = fmaf(fv.y, wv.y, acc);
                acc = fmaf(fv.z, wv.z, acc);
                acc = fmaf(fv.w, wv.w, acc);
            }
#pragma unroll
            for (int off = 16; off > 0; off >>= 1)
                acc += __shfl_xor_sync(0xffffffffu, acc, off);
            if (lane == 0) slog[task] = acc + bias[c];
        }
    }
    __syncthreads();

    if (tid < 4) {
        const float* l = slog + 10 * tid;
        float mx = l[0];
#pragma unroll
        for (int c = 1; c < 10; c++) mx = fmaxf(mx, l[c]);
        float se = 0.0f;
#pragma unroll
        for (int c = 0; c < 10; c++) se += expf(l[c] - mx);
        slse[tid] = mx + logf(se);
    }
    __syncthreads();

    if (tid < 40) {
        const int img = tid / 10;
        const int b = b0 + img;
        if (b < B)
            out[(size_t)b * 10 + (tid % 10)] = slog[tid] - slse[img];
    }
}

extern "C" void kernel_launch(void* const* d_in, const int* in_sizes, int n_in,
                              void* d_out, int out_size) {
    const float* x    = (const float*)d_in[0];   // (B,1,28,28)
    const float* vp   = (const float*)d_in[1];   // (3,8)
    const float* W    = (const float*)d_in[2];   // (10,784)
    const float* bias = (const float*)d_in[3];   // (10,)
    float* out = (float*)d_out;

    const int B = in_sizes[0] / 784;
    precompute_A_fast_kernel<<<1, 256>>>(vp);
    quanv_fused8_kernel<<<(B + 3) / 4, 224>>>(x, W, bias, out, B);
}